// round 8
// baseline (speedup 1.0000x reference)
#include <cuda_runtime.h>
#include <cstdint>

// Problem constants (fixed by the reference).
#define BB 32
#define TT 2000
#define LL 256
#define HH 512
#define THRESH 0.95f
#define T4 500          // float4 groups in T
#define NCHUNK 10
#define CFRM 200        // frames per chunk
#define CGRP 50         // float4 groups per chunk

// Scratch (allocation-free rule: __device__ globals).
__device__ float g_walpha[BB * TT];   // rescaled alphas
__device__ int4  g_rec[BB * LL];      // {seg_start, seg_end, carry_bits, cur_bits}
__device__ int   g_cnt[BB];           // fires per batch (clamped to LL)
__device__ int   g_tokrdy[BB];        // tokens released (300 = final sentinel)

__global__ void cif_reset()
{
    if (threadIdx.x < BB) g_tokrdy[threadIdx.x] = 0;
}

// One CIF recurrence step, exact reference f32 sequence:
//   add.f32 -> {setp.ge ; sub.f32 in parallel} -> selp.f32 (pred-as-data)
__device__ __forceinline__ void cif_step(float& integ, float a, float& ni_out)
{
    float ni, nim;
    asm("add.f32 %0, %2, %3;\n\t"
        "sub.f32 %1, %0, 0f3F800000;"            // nim = ni - 1.0f (exact at fire)
        : "=f"(ni), "=f"(nim) : "f"(integ), "f"(a));
    asm("{\n\t"
        ".reg .pred p;\n\t"
        "setp.ge.f32 p, %1, 0f3F733333;\n\t"     // ni >= 0.95f
        "selp.f32 %0, %2, %1, p;\n\t"
        "}"
        : "=f"(integ) : "f"(ni), "f"(nim));
    ni_out = ni;
}

// ---------------------------------------------------------------------------
// Fused kernel. Blocks [0,32): scan role (serial recurrence + progressive
// record publishing). Blocks [32, 32+8192): gather role (spin until token
// released, then stream the segment).
// ---------------------------------------------------------------------------
__global__ void __launch_bounds__(128, 12) cif_fused(
    const float* __restrict__ hidden,   // [B,T,H]
    const float* __restrict__ alphas,   // [B,T]
    const int*   __restrict__ tlen,     // [B]
    float* __restrict__ out)            // [B,L,H]
{
    __shared__ __align__(16) float s_alpha[TT];
    __shared__ __align__(16) float s_ni[TT];
    __shared__ double s_wred[4];
    __shared__ float  s_scale;
    __shared__ int    s_fidx[LL];
    __shared__ int    s_wc[3];
    __shared__ int    s_chunkdone;
    __shared__ int    s_obs;

    const int tid  = threadIdx.x;
    const int lane = tid & 31;

    if (blockIdx.x < BB) {
        // ================= SCAN ROLE =================
        const int b = blockIdx.x;
        if (tid == 0) s_chunkdone = 0;

        // ---- Phase 1: load alphas, double-sum, rescale, spill walpha ----
        const float4* ain = reinterpret_cast<const float4*>(alphas + b * TT);
        float4* asm4 = reinterpret_cast<float4*>(s_alpha);
        double local = 0.0;
        #pragma unroll
        for (int i = 0; i < 4; ++i) {
            const int idx = tid + i * 128;
            if (idx < T4) {
                const float4 v = ain[idx];
                asm4[idx] = v;
                local += (double)v.x + (double)v.y + (double)v.z + (double)v.w;
            }
        }
        #pragma unroll
        for (int off = 16; off > 0; off >>= 1)
            local += __shfl_down_sync(0xffffffffu, local, off);
        if (lane == 0) s_wred[tid >> 5] = local;
        __syncthreads();
        if (tid == 0) {
            const double s = s_wred[0] + s_wred[1] + s_wred[2] + s_wred[3];
            s_scale = __fdiv_rn((float)tlen[b], (float)s);
        }
        __syncthreads();
        const float scale = s_scale;
        float4* wout = reinterpret_cast<float4*>(g_walpha + b * TT);
        #pragma unroll
        for (int i = 0; i < 4; ++i) {
            const int idx = tid + i * 128;
            if (idx < T4) {
                float4 v = asm4[idx];
                v.x = __fmul_rn(v.x, scale); v.y = __fmul_rn(v.y, scale);
                v.z = __fmul_rn(v.z, scale); v.w = __fmul_rn(v.w, scale);
                asm4[idx] = v;
                wout[idx] = v;
            }
        }
        __syncthreads();

        if (tid == 0) {
            // ---- Phase 2: serial recurrence, chunked publishing ----
            float integ = 0.0f;
            const float4* a4 = reinterpret_cast<const float4*>(s_alpha);
            float4* n4 = reinterpret_cast<float4*>(s_ni);
            float4 av = a4[0];
            int g = 0;
            for (int c = 0; c < NCHUNK; ++c) {
                for (int gg = 0; gg < CGRP; ++gg, ++g) {
                    const float4 nx = a4[(g + 1 < T4) ? g + 1 : g];  // prefetch
                    float4 nv;
                    cif_step(integ, av.x, nv.x);
                    cif_step(integ, av.y, nv.y);
                    cif_step(integ, av.z, nv.z);
                    cif_step(integ, av.w, nv.w);
                    n4[g] = nv;
                    av = nx;
                }
                __threadfence_block();
                *(volatile int*)&s_chunkdone = c + 1;
            }
        } else if (tid >= 32) {
            // ---- Helper warps: per-chunk record rebuild + release ----
            const int h  = tid - 32;         // 0..95
            const int wi = (tid >> 5) - 1;   // helper warp 0..2
            int total = 0;
            for (int c = 0; c < NCHUNK; ++c) {
                while (*(volatile int*)&s_chunkdone < c + 1) {}
                __threadfence_block();
                const int base = c * CFRM;
                int myf[3]; int nf = 0;
                #pragma unroll
                for (int j = 0; j < 3; ++j) {
                    const int idx = 3 * h + j;
                    if (idx < CFRM) {
                        const int t = base + idx;
                        if (s_ni[t] >= THRESH) myf[nf++] = t;
                    }
                }
                int x = nf;
                #pragma unroll
                for (int d = 1; d < 32; d <<= 1) {
                    const int y = __shfl_up_sync(0xffffffffu, x, d);
                    if (lane >= d) x += y;
                }
                if (lane == 31) s_wc[wi] = x;
                asm volatile("bar.sync 1, 96;" ::: "memory");
                int wbase = 0, ctotal = 0;
                #pragma unroll
                for (int w = 0; w < 3; ++w) {
                    const int wv = s_wc[w];
                    if (w < wi) wbase += wv;
                    ctotal += wv;
                }
                const int kk0 = total + wbase + x - nf;
                for (int i = 0; i < nf; ++i) {
                    const int K = kk0 + i;
                    if (K < LL) s_fidx[K] = myf[i];
                }
                asm volatile("bar.sync 1, 96;" ::: "memory");
                for (int i = 0; i < nf; ++i) {
                    const int K = kk0 + i;
                    if (K < LL) {
                        const int t = myf[i];
                        float iold = 0.0f;
                        if (t > 0) {
                            const float np = s_ni[t - 1];
                            iold = (np >= THRESH) ? __fsub_rn(np, 1.0f) : np;
                        }
                        const float cur = __fsub_rn(1.0f, iold);
                        int pred = -1; float carry = 0.0f;
                        if (K > 0) {
                            pred = s_fidx[K - 1];
                            float pi = 0.0f;
                            if (pred > 0) {
                                const float np = s_ni[pred - 1];
                                pi = (np >= THRESH) ? __fsub_rn(np, 1.0f) : np;
                            }
                            carry = __fsub_rn(s_alpha[pred], __fsub_rn(1.0f, pi));
                        }
                        g_rec[b * LL + K] =
                            make_int4(pred, t, __float_as_int(carry), __float_as_int(cur));
                    }
                }
                total += ctotal;
                __threadfence();                       // my g_rec writes -> gpu scope
                asm volatile("bar.sync 1, 96;" ::: "memory");
                if (h == 0) {
                    const int rdy = (total < LL) ? total : LL;
                    if (c == NCHUNK - 1) {
                        g_cnt[b] = rdy;
                        __threadfence();
                        *(volatile int*)&g_tokrdy[b] = 300;   // sentinel
                    } else {
                        *(volatile int*)&g_tokrdy[b] = rdy;
                    }
                }
            }
        }
        return;
    }

    // ================= GATHER ROLE =================
    const int gb = blockIdx.x - BB;
    const int b  = gb & 31;        // low bids spread across batches
    const int k  = gb >> 5;        // low bids = low tokens (release order)

    if (tid == 0) {
        int v = *(volatile int*)&g_tokrdy[b];
        while (v <= k) { __nanosleep(256); v = *(volatile int*)&g_tokrdy[b]; }
        __threadfence();           // order subsequent reads after observation
        s_obs = v;
    }
    __syncthreads();
    const int obs = s_obs;
    const bool valid = (obs <= LL) || (k < g_cnt[b]);

    const int c = tid * 4;         // channel base
    float4 acc = make_float4(0.f, 0.f, 0.f, 0.f);

    if (valid) {
        const int4 r = g_rec[b * LL + k];
        const int   s  = r.x;
        const int   e  = r.y;
        const float wc = __int_as_float(r.z);
        const float we = __int_as_float(r.w);

        const float* hb = hidden + (size_t)b * TT * HH;
        const float* wa = g_walpha + b * TT;

        if (s >= 0) {
            const float4 h4 = __ldcs(reinterpret_cast<const float4*>(hb + (size_t)s * HH + c));
            acc.x += wc * h4.x; acc.y += wc * h4.y; acc.z += wc * h4.z; acc.w += wc * h4.w;
        }
        #pragma unroll 4
        for (int t = s + 1; t < e; ++t) {
            const float w = wa[t];
            const float4 h4 = __ldcs(reinterpret_cast<const float4*>(hb + (size_t)t * HH + c));
            acc.x += w * h4.x; acc.y += w * h4.y; acc.z += w * h4.z; acc.w += w * h4.w;
        }
        {
            const float4 h4 = __ldcs(reinterpret_cast<const float4*>(hb + (size_t)e * HH + c));
            acc.x += we * h4.x; acc.y += we * h4.y; acc.z += we * h4.z; acc.w += we * h4.w;
        }
    }
    __stcs(reinterpret_cast<float4*>(out + ((size_t)b * LL + k) * HH + c), acc);
}

// ---------------------------------------------------------------------------
extern "C" void kernel_launch(void* const* d_in, const int* in_sizes, int n_in,
                              void* d_out, int out_size)
{
    const float* hidden = (const float*)d_in[0];   // [B,T,H] f32
    const float* alphas = (const float*)d_in[1];   // [B,T]   f32
    const int*   tlen   = (const int*)  d_in[2];   // [B]     i32
    float* out = (float*)d_out;                    // [B,L,H] f32

    cif_reset<<<1, 32>>>();
    cif_fused<<<BB + BB * LL, 128>>>(hidden, alphas, tlen, out);
}

// round 9
// speedup vs baseline: 1.4729x; 1.4729x over previous
#include <cuda_runtime.h>
#include <cstdint>

// Problem constants (fixed by the reference).
#define BB 32
#define TT 2000
#define LL 256
#define HH 512
#define NTHR 256
#define FRAMES_PER_THR 8   // 256*8 = 2048 >= 2000
#define T4 (TT / 4)        // 500 float4 groups
#define THRESH 0.95f
#define NTOK (BB * LL)     // 8192 tokens
#define GBLK 2368          // 148 SMs * 16 CTAs

// Scratch (allocation-free rule: __device__ globals).
__device__ float g_walpha[BB * TT];   // rescaled alphas
__device__ int4  g_rec[BB * LL];      // {seg_start, seg_end, carry_bits, cur_bits}
__device__ int   g_cnt[BB];           // fires per batch (clamped to LL)
__device__ int   g_work;              // work-stealing counter (reset by scan)

// One CIF recurrence step, forced to the short data chain:
//   add.f32 -> {setp.ge ; sub.f32 in parallel} -> selp.f32 (pred-as-data)
__device__ __forceinline__ void cif_step(float& integ, float a, float& ni_out)
{
    float ni, nim;
    asm("add.f32 %0, %2, %3;\n\t"
        "sub.f32 %1, %0, 0f3F800000;"            // nim = ni - 1.0f
        : "=f"(ni), "=f"(nim) : "f"(integ), "f"(a));
    asm("{\n\t"
        ".reg .pred p;\n\t"
        "setp.ge.f32 p, %1, 0f3F733333;\n\t"     // ni >= 0.95f
        "selp.f32 %0, %2, %1, p;\n\t"
        "}"
        : "=f"(integ) : "f"(ni), "f"(nim));
    ni_out = ni;
}

// ---------------------------------------------------------------------------
// Kernel 1: per-batch rescale + minimal serial recurrence + parallel rebuild.
// (R7 form; also resets the gather work counter.)
// ---------------------------------------------------------------------------
__global__ void __launch_bounds__(NTHR, 1) cif_scan_kernel(
    const float* __restrict__ alphas,   // [B,T]
    const int*   __restrict__ tlen)     // [B]
{
    __shared__ __align__(16) float s_alpha[TT];
    __shared__ __align__(16) float s_ni[TT];
    __shared__ double s_wred[8];
    __shared__ float  s_scale;
    __shared__ int    s_tsum[NTHR];
    __shared__ int    s_fidx[LL];
    __shared__ int    s_cnt;

    const int b    = blockIdx.x;
    const int tid  = threadIdx.x;
    const int lane = tid & 31;
    const int wid  = tid >> 5;

    if (b == 0 && tid == 0) g_work = 0;   // reset for the following gather

    // ---- Phase 1: load alphas (float4), double sum via warp shuffles ----
    const float4* ain = reinterpret_cast<const float4*>(alphas + b * TT);
    float4* asm4 = reinterpret_cast<float4*>(s_alpha);
    double local = 0.0;
    #pragma unroll
    for (int i = 0; i < 2; ++i) {
        const int idx = tid + i * NTHR;
        if (idx < T4) {
            const float4 v = ain[idx];
            asm4[idx] = v;
            local += (double)v.x + (double)v.y + (double)v.z + (double)v.w;
        }
    }
    #pragma unroll
    for (int off = 16; off > 0; off >>= 1)
        local += __shfl_down_sync(0xffffffffu, local, off);
    if (lane == 0) s_wred[wid] = local;
    __syncthreads();
    if (tid == 0) {
        double s = 0.0;
        #pragma unroll
        for (int w = 0; w < 8; ++w) s += s_wred[w];
        s_scale = __fdiv_rn((float)tlen[b], (float)s);
    }
    __syncthreads();

    // ---- Rescale (smem + spill to global) ----
    const float scale = s_scale;
    float4* wout = reinterpret_cast<float4*>(g_walpha + b * TT);
    #pragma unroll
    for (int i = 0; i < 2; ++i) {
        const int idx = tid + i * NTHR;
        if (idx < T4) {
            float4 v = asm4[idx];
            v.x = __fmul_rn(v.x, scale); v.y = __fmul_rn(v.y, scale);
            v.z = __fmul_rn(v.z, scale); v.w = __fmul_rn(v.w, scale);
            asm4[idx] = v;
            wout[idx] = v;
        }
    }
    __syncthreads();

    // ---- Phase 2: minimal serial recurrence (thread 0), prefetched ----
    if (tid == 0) {
        float integ = 0.0f;
        const float4* a4 = reinterpret_cast<const float4*>(s_alpha);
        float4* n4 = reinterpret_cast<float4*>(s_ni);
        float4 av = a4[0];
        #pragma unroll 2
        for (int t4 = 0; t4 < T4; ++t4) {
            const int nidx = (t4 + 1 < T4) ? t4 + 1 : t4;
            const float4 nx = a4[nidx];       // prefetch off-chain
            float4 nv;
            cif_step(integ, av.x, nv.x);
            cif_step(integ, av.y, nv.y);
            cif_step(integ, av.z, nv.z);
            cif_step(integ, av.w, nv.w);
            n4[t4] = nv;
            av = nx;
        }
    }
    __syncthreads();

    // ---- Phase 3: parallel rebuild of fire records from ni_t ----
    const int t0 = tid * FRAMES_PER_THR;
    int cnt_local = 0;
    #pragma unroll
    for (int j = 0; j < FRAMES_PER_THR; ++j) {
        const int t = t0 + j;
        if (t < TT && s_ni[t] >= THRESH) ++cnt_local;
    }
    s_tsum[tid] = cnt_local;
    __syncthreads();

    {   // exclusive prefix sum over 256 counts
        int v = s_tsum[tid];
        int x = v;
        #pragma unroll
        for (int d = 1; d < 32; d <<= 1) {
            int y = __shfl_up_sync(0xffffffffu, x, d);
            if (lane >= d) x += y;
        }
        __syncthreads();
        if (lane == 31) s_tsum[wid] = x;
        __syncthreads();
        int warp_base = 0, total = 0;
        #pragma unroll
        for (int w = 0; w < 8; ++w) {
            const int wv = s_tsum[w];
            warp_base += (w < wid) ? wv : 0;
            total += wv;
        }
        __syncthreads();
        s_tsum[tid] = warp_base + x - v;
        if (tid == 0) s_cnt = (total < LL) ? total : LL;
    }
    __syncthreads();

    {   // compact fire frame indices
        int k = s_tsum[tid];
        #pragma unroll
        for (int j = 0; j < FRAMES_PER_THR; ++j) {
            const int t = t0 + j;
            if (t < TT && s_ni[t] >= THRESH) {
                if (k < LL) s_fidx[k] = t;
                ++k;
            }
        }
    }
    __syncthreads();

    // Build records with exact-f32 reconstruction of weights.
    const int cnt = s_cnt;
    if (tid < LL) {
        int4 r = make_int4(0, -1, 0, 0);
        if (tid < cnt) {
            const int t = s_fidx[tid];
            float iold = 0.0f;
            if (t > 0) {
                const float np = s_ni[t - 1];
                iold = (np >= THRESH) ? __fsub_rn(np, 1.0f) : np;
            }
            const float cur = __fsub_rn(1.0f, iold);
            float carry = 0.0f;
            int prev = -1;
            if (tid > 0) {
                prev = s_fidx[tid - 1];
                float piold = 0.0f;
                if (prev > 0) {
                    const float np = s_ni[prev - 1];
                    piold = (np >= THRESH) ? __fsub_rn(np, 1.0f) : np;
                }
                const float pcur = __fsub_rn(1.0f, piold);
                carry = __fsub_rn(s_alpha[prev], pcur);
            }
            r.x = prev;
            r.y = t;
            r.z = __float_as_int(carry);
            r.w = __float_as_int(cur);
        }
        g_rec[b * LL + tid] = r;
    }
    if (tid == 0) g_cnt[b] = cnt;
}

// ---------------------------------------------------------------------------
// Kernel 2: persistent work-stealing gather. Each CTA grabs token indices
// from g_work; body is the R3 measured-best form (plain loads, unroll 4).
// ---------------------------------------------------------------------------
__global__ void __launch_bounds__(128) cif_gather_kernel(
    const float* __restrict__ hidden,   // [B,T,H]
    float* __restrict__ out)            // [B,L,H]
{
    __shared__ int s_i;
    const int tid = threadIdx.x;
    const int c   = tid * 4;            // channel base

    for (;;) {
        if (tid == 0) s_i = atomicAdd(&g_work, 1);
        __syncthreads();
        const int i = s_i;
        __syncthreads();                // all threads read s_i before next write
        if (i >= NTOK) return;

        const int b = i & (BB - 1);     // same-k tokens spread across batches
        const int k = i >> 5;

        float4 acc = make_float4(0.f, 0.f, 0.f, 0.f);

        if (k < g_cnt[b]) {
            const int4 r = g_rec[b * LL + k];
            const int   s  = r.x;
            const int   e  = r.y;
            const float wc = __int_as_float(r.z);
            const float we = __int_as_float(r.w);

            const float* hb = hidden + (size_t)b * TT * HH;
            const float* wa = g_walpha + b * TT;

            if (s >= 0) {
                const float4 h4 = *reinterpret_cast<const float4*>(hb + (size_t)s * HH + c);
                acc.x += wc * h4.x; acc.y += wc * h4.y;
                acc.z += wc * h4.z; acc.w += wc * h4.w;
            }
            #pragma unroll 4
            for (int t = s + 1; t < e; ++t) {
                const float w = wa[t];
                const float4 h4 = *reinterpret_cast<const float4*>(hb + (size_t)t * HH + c);
                acc.x += w * h4.x; acc.y += w * h4.y;
                acc.z += w * h4.z; acc.w += w * h4.w;
            }
            {
                const float4 h4 = *reinterpret_cast<const float4*>(hb + (size_t)e * HH + c);
                acc.x += we * h4.x; acc.y += we * h4.y;
                acc.z += we * h4.z; acc.w += we * h4.w;
            }
        }
        *reinterpret_cast<float4*>(out + ((size_t)b * LL + k) * HH + c) = acc;
    }
}

// ---------------------------------------------------------------------------
extern "C" void kernel_launch(void* const* d_in, const int* in_sizes, int n_in,
                              void* d_out, int out_size)
{
    const float* hidden = (const float*)d_in[0];   // [B,T,H] f32
    const float* alphas = (const float*)d_in[1];   // [B,T]   f32
    const int*   tlen   = (const int*)  d_in[2];   // [B]     i32
    float* out = (float*)d_out;                    // [B,L,H] f32

    cif_scan_kernel<<<BB, NTHR>>>(alphas, tlen);
    cif_gather_kernel<<<GBLK, 128>>>(hidden, out);
}

// round 10
// speedup vs baseline: 1.5065x; 1.0228x over previous
#include <cuda_runtime.h>
#include <cstdint>

// Problem constants (fixed by the reference).
#define BB 32
#define TT 2000
#define LL 256
#define HH 512
#define NTHR 256
#define FRAMES_PER_THR 8   // 256*8 = 2048 >= 2000
#define T4 (TT / 4)        // 500 float4 groups
#define THRESH 0.95f
#define NTOK (BB * LL)     // 8192 tokens
#define GBLK 2368          // 148 SMs * 16 CTAs

// Prefetch role: 1000 blocks x 256 thr x 4 prefetches x 128B = 131,072,000 B
// == sizeof(hidden) exactly.
#define NPF 1000
#define PF_PER_THR 4

// Scratch (allocation-free rule: __device__ globals).
__device__ float g_walpha[BB * TT];   // rescaled alphas
__device__ int4  g_rec[BB * LL];      // {seg_start, seg_end, carry_bits, cur_bits}
__device__ int   g_cnt[BB];           // fires per batch (clamped to LL)
__device__ int   g_work;              // work-stealing counter (reset by scan)

// One CIF recurrence step, forced to the short data chain:
//   add.f32 -> {setp.ge ; sub.f32 in parallel} -> selp.f32 (pred-as-data)
__device__ __forceinline__ void cif_step(float& integ, float a, float& ni_out)
{
    float ni, nim;
    asm("add.f32 %0, %2, %3;\n\t"
        "sub.f32 %1, %0, 0f3F800000;"            // nim = ni - 1.0f
        : "=f"(ni), "=f"(nim) : "f"(integ), "f"(a));
    asm("{\n\t"
        ".reg .pred p;\n\t"
        "setp.ge.f32 p, %1, 0f3F733333;\n\t"     // ni >= 0.95f
        "selp.f32 %0, %2, %1, p;\n\t"
        "}"
        : "=f"(integ) : "f"(ni), "f"(nim));
    ni_out = ni;
}

// ---------------------------------------------------------------------------
// Kernel 1: blocks [0,32) = scan role (rescale + serial recurrence + rebuild).
// Blocks [32, 32+NPF) = L2-prefetch role: pull hidden into L2 under the
// scan's serial shadow so the gather kernel reads it at LTS bandwidth.
// ---------------------------------------------------------------------------
__global__ void __launch_bounds__(NTHR, 1) cif_scan_kernel(
    const float* __restrict__ hidden,   // [B,T,H] (prefetch only)
    const float* __restrict__ alphas,   // [B,T]
    const int*   __restrict__ tlen)     // [B]
{
    const int tid  = threadIdx.x;

    if (blockIdx.x >= BB) {
        // ---- Prefetch role: 128 KB contiguous slice per block ----
        const size_t base = (size_t)(blockIdx.x - BB) * (NTHR * PF_PER_THR * 128)
                          + (size_t)tid * 128;
        const char* p = reinterpret_cast<const char*>(hidden) + base;
        #pragma unroll
        for (int i = 0; i < PF_PER_THR; ++i)
            asm volatile("prefetch.global.L2 [%0];"
                         :: "l"(p + (size_t)i * NTHR * 128));
        return;
    }

    __shared__ __align__(16) float s_alpha[TT];
    __shared__ __align__(16) float s_ni[TT];
    __shared__ double s_wred[8];
    __shared__ float  s_scale;
    __shared__ int    s_tsum[NTHR];
    __shared__ int    s_fidx[LL];
    __shared__ int    s_cnt;

    const int b    = blockIdx.x;
    const int lane = tid & 31;
    const int wid  = tid >> 5;

    if (b == 0 && tid == 0) g_work = 0;   // reset for the following gather

    // ---- Phase 1: load alphas (float4), double sum via warp shuffles ----
    const float4* ain = reinterpret_cast<const float4*>(alphas + b * TT);
    float4* asm4 = reinterpret_cast<float4*>(s_alpha);
    double local = 0.0;
    #pragma unroll
    for (int i = 0; i < 2; ++i) {
        const int idx = tid + i * NTHR;
        if (idx < T4) {
            const float4 v = ain[idx];
            asm4[idx] = v;
            local += (double)v.x + (double)v.y + (double)v.z + (double)v.w;
        }
    }
    #pragma unroll
    for (int off = 16; off > 0; off >>= 1)
        local += __shfl_down_sync(0xffffffffu, local, off);
    if (lane == 0) s_wred[wid] = local;
    __syncthreads();
    if (tid == 0) {
        double s = 0.0;
        #pragma unroll
        for (int w = 0; w < 8; ++w) s += s_wred[w];
        s_scale = __fdiv_rn((float)tlen[b], (float)s);
    }
    __syncthreads();

    // ---- Rescale (smem + spill to global) ----
    const float scale = s_scale;
    float4* wout = reinterpret_cast<float4*>(g_walpha + b * TT);
    #pragma unroll
    for (int i = 0; i < 2; ++i) {
        const int idx = tid + i * NTHR;
        if (idx < T4) {
            float4 v = asm4[idx];
            v.x = __fmul_rn(v.x, scale); v.y = __fmul_rn(v.y, scale);
            v.z = __fmul_rn(v.z, scale); v.w = __fmul_rn(v.w, scale);
            asm4[idx] = v;
            wout[idx] = v;
        }
    }
    __syncthreads();

    // ---- Phase 2: minimal serial recurrence (thread 0), prefetched ----
    if (tid == 0) {
        float integ = 0.0f;
        const float4* a4 = reinterpret_cast<const float4*>(s_alpha);
        float4* n4 = reinterpret_cast<float4*>(s_ni);
        float4 av = a4[0];
        #pragma unroll 2
        for (int t4 = 0; t4 < T4; ++t4) {
            const int nidx = (t4 + 1 < T4) ? t4 + 1 : t4;
            const float4 nx = a4[nidx];       // prefetch off-chain
            float4 nv;
            cif_step(integ, av.x, nv.x);
            cif_step(integ, av.y, nv.y);
            cif_step(integ, av.z, nv.z);
            cif_step(integ, av.w, nv.w);
            n4[t4] = nv;
            av = nx;
        }
    }
    __syncthreads();

    // ---- Phase 3: parallel rebuild of fire records from ni_t ----
    const int t0 = tid * FRAMES_PER_THR;
    int cnt_local = 0;
    #pragma unroll
    for (int j = 0; j < FRAMES_PER_THR; ++j) {
        const int t = t0 + j;
        if (t < TT && s_ni[t] >= THRESH) ++cnt_local;
    }
    s_tsum[tid] = cnt_local;
    __syncthreads();

    {   // exclusive prefix sum over 256 counts
        int v = s_tsum[tid];
        int x = v;
        #pragma unroll
        for (int d = 1; d < 32; d <<= 1) {
            int y = __shfl_up_sync(0xffffffffu, x, d);
            if (lane >= d) x += y;
        }
        __syncthreads();
        if (lane == 31) s_tsum[wid] = x;
        __syncthreads();
        int warp_base = 0, total = 0;
        #pragma unroll
        for (int w = 0; w < 8; ++w) {
            const int wv = s_tsum[w];
            warp_base += (w < wid) ? wv : 0;
            total += wv;
        }
        __syncthreads();
        s_tsum[tid] = warp_base + x - v;
        if (tid == 0) s_cnt = (total < LL) ? total : LL;
    }
    __syncthreads();

    {   // compact fire frame indices
        int k = s_tsum[tid];
        #pragma unroll
        for (int j = 0; j < FRAMES_PER_THR; ++j) {
            const int t = t0 + j;
            if (t < TT && s_ni[t] >= THRESH) {
                if (k < LL) s_fidx[k] = t;
                ++k;
            }
        }
    }
    __syncthreads();

    // Build records with exact-f32 reconstruction of weights.
    const int cnt = s_cnt;
    if (tid < LL) {
        int4 r = make_int4(0, -1, 0, 0);
        if (tid < cnt) {
            const int t = s_fidx[tid];
            float iold = 0.0f;
            if (t > 0) {
                const float np = s_ni[t - 1];
                iold = (np >= THRESH) ? __fsub_rn(np, 1.0f) : np;
            }
            const float cur = __fsub_rn(1.0f, iold);
            float carry = 0.0f;
            int prev = -1;
            if (tid > 0) {
                prev = s_fidx[tid - 1];
                float piold = 0.0f;
                if (prev > 0) {
                    const float np = s_ni[prev - 1];
                    piold = (np >= THRESH) ? __fsub_rn(np, 1.0f) : np;
                }
                const float pcur = __fsub_rn(1.0f, piold);
                carry = __fsub_rn(s_alpha[prev], pcur);
            }
            r.x = prev;
            r.y = t;
            r.z = __float_as_int(carry);
            r.w = __float_as_int(cur);
        }
        g_rec[b * LL + tid] = r;
    }
    if (tid == 0) g_cnt[b] = cnt;
}

// ---------------------------------------------------------------------------
// Kernel 2: persistent work-stealing gather (R9 measured-best form).
// ---------------------------------------------------------------------------
__global__ void __launch_bounds__(128) cif_gather_kernel(
    const float* __restrict__ hidden,   // [B,T,H]
    float* __restrict__ out)            // [B,L,H]
{
    __shared__ int s_i;
    const int tid = threadIdx.x;
    const int c   = tid * 4;            // channel base

    for (;;) {
        if (tid == 0) s_i = atomicAdd(&g_work, 1);
        __syncthreads();
        const int i = s_i;
        __syncthreads();                // all threads read s_i before next write
        if (i >= NTOK) return;

        const int b = i & (BB - 1);     // same-k tokens spread across batches
        const int k = i >> 5;

        float4 acc = make_float4(0.f, 0.f, 0.f, 0.f);

        if (k < g_cnt[b]) {
            const int4 r = g_rec[b * LL + k];
            const int   s  = r.x;
            const int   e  = r.y;
            const float wc = __int_as_float(r.z);
            const float we = __int_as_float(r.w);

            const float* hb = hidden + (size_t)b * TT * HH;
            const float* wa = g_walpha + b * TT;

            if (s >= 0) {
                const float4 h4 = *reinterpret_cast<const float4*>(hb + (size_t)s * HH + c);
                acc.x += wc * h4.x; acc.y += wc * h4.y;
                acc.z += wc * h4.z; acc.w += wc * h4.w;
            }
            #pragma unroll 4
            for (int t = s + 1; t < e; ++t) {
                const float w = wa[t];
                const float4 h4 = *reinterpret_cast<const float4*>(hb + (size_t)t * HH + c);
                acc.x += w * h4.x; acc.y += w * h4.y;
                acc.z += w * h4.z; acc.w += w * h4.w;
            }
            {
                const float4 h4 = *reinterpret_cast<const float4*>(hb + (size_t)e * HH + c);
                acc.x += we * h4.x; acc.y += we * h4.y;
                acc.z += we * h4.z; acc.w += we * h4.w;
            }
        }
        *reinterpret_cast<float4*>(out + ((size_t)b * LL + k) * HH + c) = acc;
    }
}

// ---------------------------------------------------------------------------
extern "C" void kernel_launch(void* const* d_in, const int* in_sizes, int n_in,
                              void* d_out, int out_size)
{
    const float* hidden = (const float*)d_in[0];   // [B,T,H] f32
    const float* alphas = (const float*)d_in[1];   // [B,T]   f32
    const int*   tlen   = (const int*)  d_in[2];   // [B]     i32
    float* out = (float*)d_out;                    // [B,L,H] f32

    cif_scan_kernel<<<BB + NPF, NTHR>>>(hidden, alphas, tlen);
    cif_gather_kernel<<<GBLK, 128>>>(hidden, out);
}